// round 8
// baseline (speedup 1.0000x reference)
#include <cuda_runtime.h>

// ---------------------------------------------------------------------------
// Swin window attention (shifted), fp32 (exact) with packed f32x2 FMA GEMMs.
// B=16, H=W=64, C=512, window 8x8 (N=64), shift 4, NW=64, BW=1024,
// HEADS=8, HD=64, QKV dim = 1536, out dim = 512.
// ---------------------------------------------------------------------------

#define BW_     1024
#define HEADS_  8
#define N_      64
#define HD_     64

// Scratch (device globals: allocation-free rule)
__device__ float g_q[BW_ * HEADS_ * N_ * HD_];   // (bw,h,n,d)
__device__ float g_k[BW_ * HEADS_ * N_ * HD_];
__device__ float g_v[BW_ * HEADS_ * N_ * HD_];
__device__ float g_y[BW_ * N_ * 512];            // (m, h*64+d), m = bw*64+n

// window token m -> row index into x / out (roll by shift=4, 8x8 windows).
// Encode gather and decode scatter use the SAME mapping (decode is the exact
// inverse composition with the +shift roll; verified algebraically).
__device__ __forceinline__ int xrow(int m) {
    int bw = m >> 6, n = m & 63;
    int b  = bw >> 6, wi = bw & 63;
    int wr = wi >> 3, wc = wi & 7;
    int r  = n  >> 3, c  = n  & 7;
    int ho = (wr * 8 + r + 4) & 63;
    int wo = (wc * 8 + c + 4) & 63;
    return (b << 12) + (ho << 6) + wo;
}

// ---- packed fp32x2 helpers (sm_103a; each lane is an exact fp32 op) -------
__device__ __forceinline__ unsigned long long pk2(float lo, float hi) {
    unsigned long long r;
    asm("mov.b64 %0, {%1, %2};" : "=l"(r) : "f"(lo), "f"(hi));
    return r;
}
__device__ __forceinline__ void upk2(unsigned long long v, float& lo, float& hi) {
    asm("mov.b64 {%0, %1}, %2;" : "=f"(lo), "=f"(hi) : "l"(v));
}
__device__ __forceinline__ void ffma2(unsigned long long& d,
                                      unsigned long long a,
                                      unsigned long long b) {
    asm("fma.rn.f32x2 %0, %1, %2, %0;" : "+l"(d) : "l"(a), "l"(b));
}

// ---------------------------------------------------------------------------
// Tiled GEMM: C[m, o] = sum_k A[m,k] * W[o,k] + bias[o]
// BM=BN=128, BK=8, 256 threads, 8x8 microtile per thread (as 8x4 f32x2 pairs).
// Double-buffered smem: exactly ONE __syncthreads per K-iteration.
// MODE 0: A = x rows gathered via xrow(m); result scattered to g_q/g_k/g_v.
// MODE 1: A = g_y rows (direct); result scattered to Out via xrow(m).
// ---------------------------------------------------------------------------
template <int MODE>
__global__ __launch_bounds__(256, 2)
void gemm512(const float* __restrict__ Ain, const float* __restrict__ Wt,
             const float* __restrict__ bias, float* __restrict__ Out)
{
    __shared__ float As[2][8 * 128];   // [buf][k][m]
    __shared__ float Bs[2][8 * 128];   // [buf][k][n]

    const int tid   = threadIdx.x;
    const int mBase = blockIdx.y * 128;
    const int nBase = blockIdx.x * 128;

    // loader assignment: each thread owns one float4 per tile per iteration
    const int mload = tid >> 1;          // 0..127
    const int k4    = (tid & 1) * 4;     // 0 or 4

    const float* arow;
    if (MODE == 0) arow = Ain + (size_t)xrow(mBase + mload) * 512 + k4;
    else           arow = g_y + (size_t)(mBase + mload) * 512 + k4;
    const float* brow = Wt + (size_t)(nBase + mload) * 512 + k4;

    const int tx = tid & 15;
    const int ty = tid >> 4;

    // accumulators: pair over j (lo = j=2*jp, hi = j=2*jp+1)
    unsigned long long accp[8][4];
#pragma unroll
    for (int i = 0; i < 8; ++i)
#pragma unroll
        for (int jp = 0; jp < 4; ++jp) accp[i][jp] = 0ull;

    // Prime buffer 0
    {
        float4 ra = *(const float4*)(arow);
        float4 rb = *(const float4*)(brow);
        As[0][(k4 + 0) * 128 + mload] = ra.x;
        As[0][(k4 + 1) * 128 + mload] = ra.y;
        As[0][(k4 + 2) * 128 + mload] = ra.z;
        As[0][(k4 + 3) * 128 + mload] = ra.w;
        Bs[0][(k4 + 0) * 128 + mload] = rb.x;
        Bs[0][(k4 + 1) * 128 + mload] = rb.y;
        Bs[0][(k4 + 2) * 128 + mload] = rb.z;
        Bs[0][(k4 + 3) * 128 + mload] = rb.w;
    }
    __syncthreads();

    int buf = 0;
#pragma unroll 1
    for (int kt = 0; kt < 64; ++kt) {
        float4 na, nb;
        if (kt < 63) {   // issue next-tile global loads early (overlap w/ math)
            na = *(const float4*)(arow + (kt + 1) * 8);
            nb = *(const float4*)(brow + (kt + 1) * 8);
        }

#pragma unroll
        for (int k = 0; k < 8; ++k) {
            float4 a0 = *(const float4*)&As[buf][k * 128 + ty * 8];
            float4 a1 = *(const float4*)&As[buf][k * 128 + ty * 8 + 4];
            float4 b0 = *(const float4*)&Bs[buf][k * 128 + tx * 8];
            float4 b1 = *(const float4*)&Bs[buf][k * 128 + tx * 8 + 4];

            unsigned long long bp[4];
            bp[0] = pk2(b0.x, b0.y);
            bp[1] = pk2(b0.z, b0.w);
            bp[2] = pk2(b1.x, b1.y);
            bp[3] = pk2(b1.z, b1.w);

            float av[8] = {a0.x, a0.y, a0.z, a0.w, a1.x, a1.y, a1.z, a1.w};
#pragma unroll
            for (int i = 0; i < 8; ++i) {
                unsigned long long ad = pk2(av[i], av[i]);
                ffma2(accp[i][0], ad, bp[0]);
                ffma2(accp[i][1], ad, bp[1]);
                ffma2(accp[i][2], ad, bp[2]);
                ffma2(accp[i][3], ad, bp[3]);
            }
        }

        if (kt < 63) {
            int nb_ = buf ^ 1;
            // Safe: every thread's last READ of buf^1 was iter kt-1's compute,
            // which precedes iter kt-1's barrier, which precedes this store.
            As[nb_][(k4 + 0) * 128 + mload] = na.x;
            As[nb_][(k4 + 1) * 128 + mload] = na.y;
            As[nb_][(k4 + 2) * 128 + mload] = na.z;
            As[nb_][(k4 + 3) * 128 + mload] = na.w;
            Bs[nb_][(k4 + 0) * 128 + mload] = nb.x;
            Bs[nb_][(k4 + 1) * 128 + mload] = nb.y;
            Bs[nb_][(k4 + 2) * 128 + mload] = nb.z;
            Bs[nb_][(k4 + 3) * 128 + mload] = nb.w;
            __syncthreads();
            buf = nb_;
        }
    }

    // unpack accumulators (one-time)
    float acc[8][8];
#pragma unroll
    for (int i = 0; i < 8; ++i)
#pragma unroll
        for (int jp = 0; jp < 4; ++jp)
            upk2(accp[i][jp], acc[i][2 * jp], acc[i][2 * jp + 1]);

    const int o0 = nBase + tx * 8;
    float bj[8];
#pragma unroll
    for (int j = 0; j < 8; ++j) bj[j] = bias[o0 + j];

    if (MODE == 0) {
        // o = t*512 + h*64 + d ; dst layout ((bw*8+h)*64 + n)*64 + d
        const int t  = o0 >> 9;
        const int h  = (o0 >> 6) & 7;
        const int d0 = o0 & 63;
        float* dst = (t == 0) ? g_q : (t == 1) ? g_k : g_v;
#pragma unroll
        for (int i = 0; i < 8; ++i) {
            int m  = mBase + ty * 8 + i;
            int bw = m >> 6, n = m & 63;
            float* p = dst + (size_t)(((bw * 8 + h) * 64 + n) * 64 + d0);
            float4 v0 = {acc[i][0] + bj[0], acc[i][1] + bj[1],
                         acc[i][2] + bj[2], acc[i][3] + bj[3]};
            float4 v1 = {acc[i][4] + bj[4], acc[i][5] + bj[5],
                         acc[i][6] + bj[6], acc[i][7] + bj[7]};
            *(float4*)(p)     = v0;
            *(float4*)(p + 4) = v1;
        }
    } else {
#pragma unroll
        for (int i = 0; i < 8; ++i) {
            int m = mBase + ty * 8 + i;
            float* p = Out + (size_t)xrow(m) * 512 + o0;
            float4 v0 = {acc[i][0] + bj[0], acc[i][1] + bj[1],
                         acc[i][2] + bj[2], acc[i][3] + bj[3]};
            float4 v1 = {acc[i][4] + bj[4], acc[i][5] + bj[5],
                         acc[i][6] + bj[6], acc[i][7] + bj[7]};
            *(float4*)(p)     = v0;
            *(float4*)(p + 4) = v1;
        }
    }
}

// ---------------------------------------------------------------------------
// Attention: one block per (window, head). scores[i,j] = k_i . q_j / 8
//            + rel_bias[h,i,j] + mask[w,i,j]; softmax over j; y = P @ V.
// K/Q/V staged transposed (d-major) in smem for conflict-free access.
// Thread layout: i = tid/4 (row), quad lane jl = tid&3 owns j = 4*jj + jl.
// Static smem = 3 * 16 KB = 49152 B.
// ---------------------------------------------------------------------------
__global__ __launch_bounds__(256)
void attn_kernel(const float* __restrict__ mask, const float* __restrict__ rel)
{
    __shared__ float KT[64 * 64];
    __shared__ float QT[64 * 64];
    __shared__ float VT[64 * 64];

    const int tid = threadIdx.x;
    const int bh  = blockIdx.x;          // bw*8 + h
    const int bw  = bh >> 3;
    const int h   = bh & 7;
    const size_t base = (size_t)bh * 4096;

#pragma unroll
    for (int p = 0; p < 4; ++p) {
        int lin = tid + p * 256;         // float4 index, 0..1023
        int n   = lin & 63;
        int d4  = (lin >> 6) * 4;
        float4 q = *(const float4*)(g_q + base + n * 64 + d4);
        float4 k = *(const float4*)(g_k + base + n * 64 + d4);
        float4 v = *(const float4*)(g_v + base + n * 64 + d4);
        QT[(d4 + 0) * 64 + n] = q.x; QT[(d4 + 1) * 64 + n] = q.y;
        QT[(d4 + 2) * 64 + n] = q.z; QT[(d4 + 3) * 64 + n] = q.w;
        KT[(d4 + 0) * 64 + n] = k.x; KT[(d4 + 1) * 64 + n] = k.y;
        KT[(d4 + 2) * 64 + n] = k.z; KT[(d4 + 3) * 64 + n] = k.w;
        VT[(d4 + 0) * 64 + n] = v.x; VT[(d4 + 1) * 64 + n] = v.y;
        VT[(d4 + 2) * 64 + n] = v.z; VT[(d4 + 3) * 64 + n] = v.w;
    }
    __syncthreads();

    const int i  = tid >> 2;
    const int jl = tid & 3;

    float s[16];
#pragma unroll
    for (int jj = 0; jj < 16; ++jj) s[jj] = 0.f;

#pragma unroll 8
    for (int d = 0; d < 64; ++d) {
        float kv = KT[d * 64 + i];
#pragma unroll
        for (int jj = 0; jj < 16; ++jj)
            s[jj] = fmaf(kv, QT[d * 64 + jj * 4 + jl], s[jj]);
    }

    // scale + relative position bias + shift mask
    const int wIdx = bw & 63;
    const float* mrow = mask + wIdx * 4096 + i * 64;
    const int ri = i >> 3, ci = i & 7;
#pragma unroll
    for (int jj = 0; jj < 16; ++jj) {
        int j  = jj * 4 + jl;
        int rj = j >> 3, cj = j & 7;
        int idx = (ri - rj + 7) * 15 + (ci - cj + 7);
        s[jj] = s[jj] * 0.125f + __ldg(rel + idx * 8 + h) + __ldg(mrow + j);
    }

    // softmax over j (64 values spread over 16 regs x 4 quad lanes)
    float mx = s[0];
#pragma unroll
    for (int jj = 1; jj < 16; ++jj) mx = fmaxf(mx, s[jj]);
    mx = fmaxf(mx, __shfl_xor_sync(0xffffffffu, mx, 1));
    mx = fmaxf(mx, __shfl_xor_sync(0xffffffffu, mx, 2));

    float sum = 0.f;
#pragma unroll
    for (int jj = 0; jj < 16; ++jj) { s[jj] = __expf(s[jj] - mx); sum += s[jj]; }
    sum += __shfl_xor_sync(0xffffffffu, sum, 1);
    sum += __shfl_xor_sync(0xffffffffu, sum, 2);
    float inv = 1.0f / sum;
#pragma unroll
    for (int jj = 0; jj < 16; ++jj) s[jj] *= inv;

    // y[i,d] = sum_j P[i,j] * V[j,d]; quad-partial then shfl reduce per d.
    float yout[16];
#pragma unroll
    for (int d = 0; d < 64; ++d) {
        float a = 0.f;
#pragma unroll
        for (int jj = 0; jj < 16; ++jj)
            a = fmaf(s[jj], VT[d * 64 + jj * 4 + jl], a);
        a += __shfl_xor_sync(0xffffffffu, a, 1);
        a += __shfl_xor_sync(0xffffffffu, a, 2);
        if ((d >> 4) == jl) yout[d & 15] = a;
    }

    // write y in (m, h*64+d) layout; each quad lane owns 16 consecutive d
    const int m = bw * 64 + i;
    float* dst = g_y + (size_t)m * 512 + h * 64 + jl * 16;
    *(float4*)(dst +  0) = {yout[ 0], yout[ 1], yout[ 2], yout[ 3]};
    *(float4*)(dst +  4) = {yout[ 4], yout[ 5], yout[ 6], yout[ 7]};
    *(float4*)(dst +  8) = {yout[ 8], yout[ 9], yout[10], yout[11]};
    *(float4*)(dst + 12) = {yout[12], yout[13], yout[14], yout[15]};
}

// ---------------------------------------------------------------------------
extern "C" void kernel_launch(void* const* d_in, const int* in_sizes, int n_in,
                              void* d_out, int out_size)
{
    const float* x        = (const float*)d_in[0];
    const float* mask     = (const float*)d_in[1];
    const float* wqkv_w   = (const float*)d_in[2];
    const float* wqkv_b   = (const float*)d_in[3];
    const float* rel_tab  = (const float*)d_in[4];
    const float* out_w    = (const float*)d_in[5];
    const float* out_b    = (const float*)d_in[6];
    float* out            = (float*)d_out;

    // 1) gather + QKV projection: (65536 x 1536) = (65536 x 512) @ W^T
    gemm512<0><<<dim3(12, 512), 256>>>(x, wqkv_w, wqkv_b, nullptr);

    // 2) attention per (window, head)
    attn_kernel<<<BW_ * HEADS_, 256>>>(mask, rel_tab);

    // 3) output projection + window-decode scatter: (65536 x 512)
    gemm512<1><<<dim3(4, 512), 256>>>(nullptr, out_w, out_b, out);
}

// round 9
// speedup vs baseline: 1.2737x; 1.2737x over previous
#include <cuda_runtime.h>
#include <cstdint>

// ---------------------------------------------------------------------------
// Swin window attention (shifted). GEMMs on tensor cores (tf32 x3 split,
// fp32-accurate); attention kernel unchanged (validated, rel_err 3.4e-7).
// B=16, H=W=64, C=512, window 8x8 (N=64), shift 4, NW=64, BW=1024,
// HEADS=8, HD=64, QKV dim = 1536, out dim = 512.
// ---------------------------------------------------------------------------

#define BW_     1024
#define HEADS_  8

// Scratch (device globals: allocation-free rule)
__device__ float g_q[BW_ * HEADS_ * 64 * 64];    // (bw,h,n,d)
__device__ float g_k[BW_ * HEADS_ * 64 * 64];
__device__ float g_v[BW_ * HEADS_ * 64 * 64];
__device__ float g_y[BW_ * 64 * 512];            // (m, h*64+d), m = bw*64+n

// window token m -> row index into x / out (roll by shift=4, 8x8 windows).
__device__ __forceinline__ int xrow(int m) {
    int bw = m >> 6, n = m & 63;
    int b  = bw >> 6, wi = bw & 63;
    int wr = wi >> 3, wc = wi & 7;
    int r  = n  >> 3, c  = n  & 7;
    int ho = (wr * 8 + r + 4) & 63;
    int wo = (wc * 8 + c + 4) & 63;
    return (b << 12) + (ho << 6) + wo;
}

// tf32 split: x = hi + lo, hi has top-11-bit mantissa (exact tf32), lo exact fp32.
__device__ __forceinline__ void tf32_split(float x, uint32_t& hi, uint32_t& lo) {
    uint32_t u = __float_as_uint(x);
    hi = u & 0xffffe000u;
    lo = __float_as_uint(x - __uint_as_float(hi));
}

__device__ __forceinline__ void mma_tf32(float* d, const uint32_t* a, const uint32_t* b) {
    asm volatile(
        "mma.sync.aligned.m16n8k8.row.col.f32.tf32.tf32.f32 "
        "{%0,%1,%2,%3}, {%4,%5,%6,%7}, {%8,%9}, {%0,%1,%2,%3};\n"
        : "+f"(d[0]), "+f"(d[1]), "+f"(d[2]), "+f"(d[3])
        : "r"(a[0]), "r"(a[1]), "r"(a[2]), "r"(a[3]), "r"(b[0]), "r"(b[1]));
}

#define SA 136   // smem row stride (floats): (136*k + m) % 32 = (8k+m)%32 -> conflict-free frags

// ---------------------------------------------------------------------------
// Tensor-core GEMM: C[m,o] = sum_k A[m,k] * W[o,k] + bias[o]
// BM=BN=128, BK=8, 256 threads = 8 warps (2 x-m, 4 x-n), warp tile 64x32.
// Per warp per k8: 16 mma tiles x 3 (hi*hi, hi*lo, lo*hi) = 48 HMMA.
// Double-buffered smem, one __syncthreads per K-iteration (proven scheme).
// MODE 0: A = x rows via xrow(m); scatter to g_q/g_k/g_v.
// MODE 1: A = g_y rows; scatter to Out via xrow(m).
// ---------------------------------------------------------------------------
template <int MODE>
__global__ __launch_bounds__(256, 1)
void gemm_tc(const float* __restrict__ Ain, const float* __restrict__ Wt,
             const float* __restrict__ bias, float* __restrict__ Out)
{
    __shared__ float As[2][8 * SA];   // [buf][k][m]
    __shared__ float Bs[2][8 * SA];   // [buf][k][n]

    const int tid   = threadIdx.x;
    const int mBase = blockIdx.y * 128;
    const int nBase = blockIdx.x * 128;

    // global->smem loader: identical ownership scheme as validated baseline
    const int mload = tid >> 1;          // 0..127
    const int k4    = (tid & 1) * 4;     // 0 or 4

    const float* arow;
    if (MODE == 0) arow = Ain + (size_t)xrow(mBase + mload) * 512 + k4;
    else           arow = g_y + (size_t)(mBase + mload) * 512 + k4;
    const float* brow = Wt + (size_t)(nBase + mload) * 512 + k4;

    const int lane = tid & 31;
    const int wid  = tid >> 5;
    const int wm   = wid & 1;            // 2 warps over m: 64 rows each
    const int wn   = wid >> 1;           // 4 warps over n: 32 cols each
    const int lq   = lane >> 2;          // 0..7
    const int lr   = lane & 3;           // 0..3

    float acc[4][4][4];                  // [mt][nt][c-reg]
#pragma unroll
    for (int mt = 0; mt < 4; ++mt)
#pragma unroll
        for (int nt = 0; nt < 4; ++nt)
#pragma unroll
            for (int c = 0; c < 4; ++c) acc[mt][nt][c] = 0.f;

    // Prime buffer 0
    {
        float4 ra = *(const float4*)(arow);
        float4 rb = *(const float4*)(brow);
        As[0][(k4 + 0) * SA + mload] = ra.x;
        As[0][(k4 + 1) * SA + mload] = ra.y;
        As[0][(k4 + 2) * SA + mload] = ra.z;
        As[0][(k4 + 3) * SA + mload] = ra.w;
        Bs[0][(k4 + 0) * SA + mload] = rb.x;
        Bs[0][(k4 + 1) * SA + mload] = rb.y;
        Bs[0][(k4 + 2) * SA + mload] = rb.z;
        Bs[0][(k4 + 3) * SA + mload] = rb.w;
    }
    __syncthreads();

    int buf = 0;
#pragma unroll 1
    for (int kt = 0; kt < 64; ++kt) {
        float4 na, nb;
        if (kt < 63) {
            na = *(const float4*)(arow + (kt + 1) * 8);
            nb = *(const float4*)(brow + (kt + 1) * 8);
        }

        // ---- load + split fragments for this k8 slab ----
        // A frag (m16 x k8), 4 m-tiles: a0=(lq,lr) a1=(lq+8,lr) a2=(lq,lr+4) a3=(lq+8,lr+4)
        uint32_t ahi[4][4], alo[4][4];
#pragma unroll
        for (int mt = 0; mt < 4; ++mt) {
            int mr = wm * 64 + mt * 16 + lq;
            float x0 = As[buf][lr * SA + mr];
            float x1 = As[buf][lr * SA + mr + 8];
            float x2 = As[buf][(lr + 4) * SA + mr];
            float x3 = As[buf][(lr + 4) * SA + mr + 8];
            tf32_split(x0, ahi[mt][0], alo[mt][0]);
            tf32_split(x1, ahi[mt][1], alo[mt][1]);
            tf32_split(x2, ahi[mt][2], alo[mt][2]);
            tf32_split(x3, ahi[mt][3], alo[mt][3]);
        }
        // B frag (k8 x n8), 4 n-tiles: b0=(k=lr, n=lq) b1=(k=lr+4, n=lq)
        uint32_t bhi[4][2], blo[4][2];
#pragma unroll
        for (int nt = 0; nt < 4; ++nt) {
            int nc = wn * 32 + nt * 8 + lq;
            float y0 = Bs[buf][lr * SA + nc];
            float y1 = Bs[buf][(lr + 4) * SA + nc];
            tf32_split(y0, bhi[nt][0], blo[nt][0]);
            tf32_split(y1, bhi[nt][1], blo[nt][1]);
        }

        // ---- 3xTF32 mma: hi*hi + hi*lo + lo*hi (lo*lo ~ 2^-22, dropped) ----
#pragma unroll
        for (int mt = 0; mt < 4; ++mt)
#pragma unroll
            for (int nt = 0; nt < 4; ++nt) {
                mma_tf32(acc[mt][nt], ahi[mt], bhi[nt]);
                mma_tf32(acc[mt][nt], ahi[mt], blo[nt]);
                mma_tf32(acc[mt][nt], alo[mt], bhi[nt]);
            }

        if (kt < 63) {
            int nb_ = buf ^ 1;
            As[nb_][(k4 + 0) * SA + mload] = na.x;
            As[nb_][(k4 + 1) * SA + mload] = na.y;
            As[nb_][(k4 + 2) * SA + mload] = na.z;
            As[nb_][(k4 + 3) * SA + mload] = na.w;
            Bs[nb_][(k4 + 0) * SA + mload] = nb.x;
            Bs[nb_][(k4 + 1) * SA + mload] = nb.y;
            Bs[nb_][(k4 + 2) * SA + mload] = nb.z;
            Bs[nb_][(k4 + 3) * SA + mload] = nb.w;
            __syncthreads();
            buf = nb_;
        }
    }

    // ---- epilogue: c0=(lq, 2lr) c1=(lq, 2lr+1) c2=(lq+8, 2lr) c3=(lq+8, 2lr+1) ----
#pragma unroll
    for (int nt = 0; nt < 4; ++nt) {
        const int o = nBase + wn * 32 + nt * 8 + 2 * lr;   // even; o,o+1 same (t,h) block
        const float b0v = __ldg(bias + o);
        const float b1v = __ldg(bias + o + 1);

        if (MODE == 0) {
            const int t  = o >> 9;
            const int h  = (o >> 6) & 7;
            const int d0 = o & 63;
            float* dst = (t == 0) ? g_q : (t == 1) ? g_k : g_v;
#pragma unroll
            for (int mt = 0; mt < 4; ++mt) {
#pragma unroll
                for (int half = 0; half < 2; ++half) {
                    int m  = mBase + wm * 64 + mt * 16 + lq + half * 8;
                    int bw = m >> 6, n = m & 63;
                    float* p = dst + (size_t)(((bw * 8 + h) * 64 + n) * 64 + d0);
                    float2 v = {acc[mt][nt][half * 2 + 0] + b0v,
                                acc[mt][nt][half * 2 + 1] + b1v};
                    *(float2*)p = v;
                }
            }
        } else {
#pragma unroll
            for (int mt = 0; mt < 4; ++mt) {
#pragma unroll
                for (int half = 0; half < 2; ++half) {
                    int m = mBase + wm * 64 + mt * 16 + lq + half * 8;
                    float* p = Out + (size_t)xrow(m) * 512 + o;
                    float2 v = {acc[mt][nt][half * 2 + 0] + b0v,
                                acc[mt][nt][half * 2 + 1] + b1v};
                    *(float2*)p = v;
                }
            }
        }
    }
}

// ---------------------------------------------------------------------------
// Attention: UNCHANGED from validated baseline (rel_err 3.4e-7).
// One block per (window, head); K/Q/V transposed in smem; quad-parallel rows.
// ---------------------------------------------------------------------------
__global__ __launch_bounds__(256)
void attn_kernel(const float* __restrict__ mask, const float* __restrict__ rel)
{
    __shared__ float KT[64 * 64];
    __shared__ float QT[64 * 64];
    __shared__ float VT[64 * 64];

    const int tid = threadIdx.x;
    const int bh  = blockIdx.x;          // bw*8 + h
    const int bw  = bh >> 3;
    const int h   = bh & 7;
    const size_t base = (size_t)bh * 4096;

#pragma unroll
    for (int p = 0; p < 4; ++p) {
        int lin = tid + p * 256;
        int n   = lin & 63;
        int d4  = (lin >> 6) * 4;
        float4 q = *(const float4*)(g_q + base + n * 64 + d4);
        float4 k = *(const float4*)(g_k + base + n * 64 + d4);
        float4 v = *(const float4*)(g_v + base + n * 64 + d4);
        QT[(d4 + 0) * 64 + n] = q.x; QT[(d4 + 1) * 64 + n] = q.y;
        QT[(d4 + 2) * 64 + n] = q.z; QT[(d4 + 3) * 64 + n] = q.w;
        KT[(d4 + 0) * 64 + n] = k.x; KT[(d4 + 1) * 64 + n] = k.y;
        KT[(d4 + 2) * 64 + n] = k.z; KT[(d4 + 3) * 64 + n] = k.w;
        VT[(d4 + 0) * 64 + n] = v.x; VT[(d4 + 1) * 64 + n] = v.y;
        VT[(d4 + 2) * 64 + n] = v.z; VT[(d4 + 3) * 64 + n] = v.w;
    }
    __syncthreads();

    const int i  = tid >> 2;
    const int jl = tid & 3;

    float s[16];
#pragma unroll
    for (int jj = 0; jj < 16; ++jj) s[jj] = 0.f;

#pragma unroll 8
    for (int d = 0; d < 64; ++d) {
        float kv = KT[d * 64 + i];
#pragma unroll
        for (int jj = 0; jj < 16; ++jj)
            s[jj] = fmaf(kv, QT[d * 64 + jj * 4 + jl], s[jj]);
    }

    const int wIdx = bw & 63;
    const float* mrow = mask + wIdx * 4096 + i * 64;
    const int ri = i >> 3, ci = i & 7;
#pragma unroll
    for (int jj = 0; jj < 16; ++jj) {
        int j  = jj * 4 + jl;
        int rj = j >> 3, cj = j & 7;
        int idx = (ri - rj + 7) * 15 + (ci - cj + 7);
        s[jj] = s[jj] * 0.125f + __ldg(rel + idx * 8 + h) + __ldg(mrow + j);
    }

    float mx = s[0];
#pragma unroll
    for (int jj = 1; jj < 16; ++jj) mx = fmaxf(mx, s[jj]);
    mx = fmaxf(mx, __shfl_xor_sync(0xffffffffu, mx, 1));
    mx = fmaxf(mx, __shfl_xor_sync(0xffffffffu, mx, 2));

    float sum = 0.f;
#pragma unroll
    for (int jj = 0; jj < 16; ++jj) { s[jj] = __expf(s[jj] - mx); sum += s[jj]; }
    sum += __shfl_xor_sync(0xffffffffu, sum, 1);
    sum += __shfl_xor_sync(0xffffffffu, sum, 2);
    float inv = 1.0f / sum;
#pragma unroll
    for (int jj = 0; jj < 16; ++jj) s[jj] *= inv;

    float yout[16];
#pragma unroll
    for (int d = 0; d < 64; ++d) {
        float a = 0.f;
#pragma unroll
        for (int jj = 0; jj < 16; ++jj)
            a = fmaf(s[jj], VT[d * 64 + jj * 4 + jl], a);
        a += __shfl_xor_sync(0xffffffffu, a, 1);
        a += __shfl_xor_sync(0xffffffffu, a, 2);
        if ((d >> 4) == jl) yout[d & 15] = a;
    }

    const int m = bw * 64 + i;
    float* dst = g_y + (size_t)m * 512 + h * 64 + jl * 16;
    *(float4*)(dst +  0) = {yout[ 0], yout[ 1], yout[ 2], yout[ 3]};
    *(float4*)(dst +  4) = {yout[ 4], yout[ 5], yout[ 6], yout[ 7]};
    *(float4*)(dst +  8) = {yout[ 8], yout[ 9], yout[10], yout[11]};
    *(float4*)(dst + 12) = {yout[12], yout[13], yout[14], yout[15]};
}

// ---------------------------------------------------------------------------
extern "C" void kernel_launch(void* const* d_in, const int* in_sizes, int n_in,
                              void* d_out, int out_size)
{
    const float* x        = (const float*)d_in[0];
    const float* mask     = (const float*)d_in[1];
    const float* wqkv_w   = (const float*)d_in[2];
    const float* wqkv_b   = (const float*)d_in[3];
    const float* rel_tab  = (const float*)d_in[4];
    const float* out_w    = (const float*)d_in[5];
    const float* out_b    = (const float*)d_in[6];
    float* out            = (float*)d_out;

    // 1) gather + QKV projection: (65536 x 1536) = (65536 x 512) @ W^T
    gemm_tc<0><<<dim3(12, 512), 256>>>(x, wqkv_w, wqkv_b, nullptr);

    // 2) attention per (window, head)
    attn_kernel<<<BW_ * HEADS_, 256>>>(mask, rel_tab);

    // 3) output projection + window-decode scatter: (65536 x 512)
    gemm_tc<1><<<dim3(4, 512), 256>>>(nullptr, out_w, out_b, out);
}